// round 14
// baseline (speedup 1.0000x reference)
#include <cuda_runtime.h>
#include <cuda_fp16.h>
#include <stdint.h>

#define B_   32
#define C_   128
#define H_   56
#define W_   56
#define O_   256
#define HW_  3136
#define TROW 28          // tiles per row
#define TPI  784         // tiles per image
#define NT   25088       // total 4x4 tiles (B_*TPI)

// Scratch (__device__ globals, allocation-free rule)
__device__ __align__(16) __half g_V[(size_t)16 * NT * 128];   // [tap][tile][c]  ~103MB
__device__ __align__(16) __half g_U[(size_t)16 * O_ * 128];   // [tap][o][c]     1MB
__device__ float g_sw[O_];

// ---------------------------------------------------------------------------
// PTX helpers (base ISA, valid on plain sm_103 target)
// ---------------------------------------------------------------------------
__device__ __forceinline__ void cp16(uint32_t dst, const void* src) {
    asm volatile("cp.async.cg.shared.global [%0], [%1], 16;\n"
                 :: "r"(dst), "l"(__cvta_generic_to_global(src)));
}
__device__ __forceinline__ void cp_commit() { asm volatile("cp.async.commit_group;\n" ::); }
template<int N> __device__ __forceinline__ void cp_wait() {
    asm volatile("cp.async.wait_group %0;\n" :: "n"(N));
}
__device__ __forceinline__ void ldsm4(uint32_t* r, uint32_t addr) {
    asm volatile("ldmatrix.sync.aligned.m8n8.x4.shared.b16 {%0,%1,%2,%3}, [%4];\n"
                 : "=r"(r[0]), "=r"(r[1]), "=r"(r[2]), "=r"(r[3]) : "r"(addr));
}
__device__ __forceinline__ void mma_f16(float* c, const uint32_t* a, uint32_t b0, uint32_t b1) {
    asm volatile("mma.sync.aligned.m16n8k16.row.col.f32.f16.f16.f32 "
                 "{%0,%1,%2,%3}, {%4,%5,%6,%7}, {%8,%9}, {%0,%1,%2,%3};\n"
                 : "+f"(c[0]), "+f"(c[1]), "+f"(c[2]), "+f"(c[3])
                 : "r"(a[0]), "r"(a[1]), "r"(a[2]), "r"(a[3]), "r"(b0), "r"(b1));
}

// Fast exact-nearest quantize: round true quotient x/s to nearest int.
__device__ __forceinline__ float qround(float v, float inv, float s, float hs) {
    float n = rintf(v * inv);
    float d = fmaf(-n, s, v);
    n += (d > hs) ? 1.f : 0.f;
    n -= (d < -hs) ? 1.f : 0.f;
    return fminf(fmaxf(n, -127.f), 127.f);
}

// ---------------------------------------------------------------------------
// 1) x -> quantize -> Winograd input transform -> g_V[tap][tile][c].
//    (R13 version — measured 50.8us.)
// ---------------------------------------------------------------------------
#define XSTRIDE 60       // bytes per (row,c) line
#define XSMEM (4 * 128 * XSTRIDE)   // 30720 B

__global__ __launch_bounds__(256) void wino_x_kernel(const float* __restrict__ x,
                                                     const float* __restrict__ sxp)
{
    extern __shared__ int8_t sq[];
    int t = threadIdx.x;
    int bi = blockIdx.x / TROW, ti = blockIdx.x % TROW;
    float s = *sxp;
    float inv = 1.0f / s;
    float hs = 0.5f * s;

    // Load + quantize: 4 rows (2ti-1..2ti+2) x 128 ch x 56 w -> int8 smem
#pragma unroll 4
    for (int i = 0; i < 28; i++) {
        int idx = t + 256 * i;             // 0..7167 = 4*128*14-1
        int w4 = idx % 14;
        int cr = idx / 14;
        int c = cr & 127, j = cr >> 7;
        int row = 2 * ti - 1 + j;
        float4 v = make_float4(0.f, 0.f, 0.f, 0.f);
        if (row >= 0 && row < H_)
            v = *(const float4*)(x + ((size_t)bi * C_ + c) * HW_ + row * W_ + w4 * 4);
        int q0 = (int)qround(v.x, inv, s, hs);
        int q1 = (int)qround(v.y, inv, s, hs);
        int q2 = (int)qround(v.z, inv, s, hs);
        int q3 = (int)qround(v.w, inv, s, hs);
        uint32_t pk = (uint32_t)(q0 & 0xFF) | ((uint32_t)(q1 & 0xFF) << 8)
                    | ((uint32_t)(q2 & 0xFF) << 16) | ((uint32_t)(q3 & 0xFF) << 24);
        *(uint32_t*)(sq + (j * 128 + c) * XSTRIDE + w4 * 4) = pk;
    }
    __syncthreads();

    // Transform: item = (tj, c)
#pragma unroll 2
    for (int i = 0; i < 14; i++) {
        int idx = t + 256 * i;             // 0..3583
        int c = idx & 127, tj = idx >> 7;
        float d[4][4];
#pragma unroll
        for (int r = 0; r < 4; r++)
#pragma unroll
            for (int wc = 0; wc < 4; wc++) {
                int w = 2 * tj - 1 + wc;
                d[r][wc] = (w >= 0 && w < W_)
                    ? (float)sq[(r * 128 + c) * XSTRIDE + w] : 0.f;
            }
        float e[4][4];
#pragma unroll
        for (int j = 0; j < 4; j++) {
            e[0][j] = d[0][j] - d[2][j];
            e[1][j] = d[1][j] + d[2][j];
            e[2][j] = d[2][j] - d[1][j];
            e[3][j] = d[1][j] - d[3][j];
        }
        float vv[4][4];
#pragma unroll
        for (int r = 0; r < 4; r++) {
            vv[r][0] = e[r][0] - e[r][2];
            vv[r][1] = e[r][1] + e[r][2];
            vv[r][2] = e[r][2] - e[r][1];
            vv[r][3] = e[r][1] - e[r][3];
        }
        int tid = bi * TPI + ti * TROW + tj;
#pragma unroll
        for (int r = 0; r < 4; r++)
#pragma unroll
            for (int j = 0; j < 4; j++)
                g_V[((size_t)(r * 4 + j) * NT + tid) * 128 + c] = __float2half_rn(vv[r][j]);
    }
}

// ---------------------------------------------------------------------------
// 2) weight: per-o dynamic scale = max|w|/127, quantize, Winograd filter
//    transform -> g_U[tap][o][c]  (fp16 exact: quarter-multiples, |.| <= 286)
// ---------------------------------------------------------------------------
__global__ __launch_bounds__(128) void wino_w_kernel(const float* __restrict__ w)
{
    int o = blockIdx.x, t = threadIdx.x;
    const float* wo = w + (size_t)o * 1152;

    float m = 0.f;
    for (int i = t; i < 1152; i += 128) m = fmaxf(m, fabsf(wo[i]));
#pragma unroll
    for (int off = 16; off; off >>= 1) m = fmaxf(m, __shfl_xor_sync(0xFFFFFFFFu, m, off));
    __shared__ float red[4];
    if ((t & 31) == 0) red[t >> 5] = m;
    __syncthreads();
    m = fmaxf(fmaxf(red[0], red[1]), fmaxf(red[2], red[3]));
    float scale = m / 127.0f;
    if (t == 0) g_sw[o] = scale;

    int c = t;   // 128 threads == 128 channels
    float g[3][3];
#pragma unroll
    for (int kh = 0; kh < 3; kh++)
#pragma unroll
        for (int kw = 0; kw < 3; kw++) {
            float q = rintf(wo[c * 9 + kh * 3 + kw] / scale);
            g[kh][kw] = fminf(fmaxf(q, -127.f), 127.f);
        }
    float f[4][3];
#pragma unroll
    for (int j = 0; j < 3; j++) {
        f[0][j] = g[0][j];
        f[1][j] = (g[0][j] + g[1][j] + g[2][j]) * 0.5f;
        f[2][j] = (g[0][j] - g[1][j] + g[2][j]) * 0.5f;
        f[3][j] = g[2][j];
    }
#pragma unroll
    for (int r = 0; r < 4; r++) {
        float u0 = f[r][0];
        float u1 = (f[r][0] + f[r][1] + f[r][2]) * 0.5f;
        float u2 = (f[r][0] - f[r][1] + f[r][2]) * 0.5f;
        float u3 = f[r][2];
        g_U[((size_t)(r * 4 + 0) * O_ + o) * 128 + c] = __float2half_rn(u0);
        g_U[((size_t)(r * 4 + 1) * O_ + o) * 128 + c] = __float2half_rn(u1);
        g_U[((size_t)(r * 4 + 2) * O_ + o) * 128 + c] = __float2half_rn(u2);
        g_U[((size_t)(r * 4 + 3) * O_ + o) * 128 + c] = __float2half_rn(u3);
    }
}

// ---------------------------------------------------------------------------
// 3) Winograd GEMM — R13 structure + zero-coeff AT fold (ONLY change):
//    CTA = 128 tiles x 64 o, 256 threads (8 warps 4m x 2n, warp 32x32).
//    3-stage single-tap cp.async ring (wait<1>).
// ---------------------------------------------------------------------------
#define GSTRIDE 272                       // bytes per 256B row (+16 pad)
#define GABYTES (128 * GSTRIDE)           // 34816
#define GBBYTES (64 * GSTRIDE)            // 17408
#define GSTAGE  (GABYTES + GBBYTES)       // 52224
#define GSMEM   (3 * GSTAGE)              // 156672 (>= epilogue 133632)

__global__ __launch_bounds__(256, 1)
void wino_gemm_kernel(const float* __restrict__ sxp,
                      const float* __restrict__ bias,
                      float* __restrict__ out)
{
    extern __shared__ char sm[];
    uint32_t sbase = (uint32_t)__cvta_generic_to_shared(sm);
    int t = threadIdx.x;
    int wid = t >> 5, l = t & 31;
    int wm = wid & 3, wn = wid >> 2;      // warp tile: 32 tiles x 32 o
    int o0 = blockIdx.x * 64;             // o-block fastest -> V shared in L2
    int tid0 = blockIdx.y * 128;

    float oacc[2][4][4][4];               // [mi][ni][q][e]
#pragma unroll
    for (int mi = 0; mi < 2; mi++)
#pragma unroll
        for (int ni = 0; ni < 4; ni++)
#pragma unroll
            for (int q = 0; q < 4; q++)
#pragma unroll
                for (int e = 0; e < 4; e++) oacc[mi][ni][q][e] = 0.f;

    uint32_t aOff0 = (uint32_t)((wm * 32 + (l & 15)) * GSTRIDE + (l >> 4) * 16);
    uint32_t aOff1 = aOff0 + 16u * GSTRIDE;
    uint32_t bOff0 = (uint32_t)(GABYTES + (wn * 32 + (l & 7) + (l >> 4) * 8) * GSTRIDE
                                + ((l >> 3) & 1) * 16);
    uint32_t bOff1 = bOff0 + 16u * GSTRIDE;

    auto load_stage = [&](int tap, int stg) {
        const __half* Vs = g_V + ((size_t)tap * NT + tid0) * 128;
        const __half* Us = g_U + ((size_t)tap * O_ + o0) * 128;
        uint32_t base = sbase + stg * GSTAGE;
#pragma unroll
        for (int i = 0; i < 8; i++) {
            int idx = t + 256 * i;        // A: 128 rows x 16 chunks
            int row = idx >> 4, jj = idx & 15;
            cp16(base + row * GSTRIDE + jj * 16, Vs + row * 128 + jj * 8);
        }
#pragma unroll
        for (int i = 0; i < 4; i++) {
            int idx = t + 256 * i;        // B: 64 rows x 16 chunks
            int row = idx >> 4, jj = idx & 15;
            cp16(base + GABYTES + row * GSTRIDE + jj * 16, Us + row * 128 + jj * 8);
        }
    };

    const float AT0[4] = {1.f, 1.f, 1.f, 0.f};
    const float AT1[4] = {0.f, 1.f, -1.f, -1.f};

    load_stage(0, 0); cp_commit();
    load_stage(1, 1); cp_commit();

#pragma unroll
    for (int tap = 0; tap < 16; tap++) {
        cp_wait<1>();
        __syncthreads();
        if (tap + 2 < 16) load_stage(tap + 2, (tap + 2) % 3);
        cp_commit();

        uint32_t base = sbase + (tap % 3) * GSTAGE;
        float mfr[2][4][4] = {};
#pragma unroll
        for (int ks = 0; ks < 8; ks++) {
            uint32_t a0[4], a1[4], b0[4], b1[4];
            ldsm4(a0, base + aOff0 + ks * 32);
            ldsm4(a1, base + aOff1 + ks * 32);
            ldsm4(b0, base + bOff0 + ks * 32);
            ldsm4(b1, base + bOff1 + ks * 32);
            mma_f16(mfr[0][0], a0, b0[0], b0[1]);
            mma_f16(mfr[0][1], a0, b0[2], b0[3]);
            mma_f16(mfr[0][2], a0, b1[0], b1[1]);
            mma_f16(mfr[0][3], a0, b1[2], b1[3]);
            mma_f16(mfr[1][0], a1, b0[0], b0[1]);
            mma_f16(mfr[1][1], a1, b0[2], b0[3]);
            mma_f16(mfr[1][2], a1, b1[0], b1[1]);
            mma_f16(mfr[1][3], a1, b1[2], b1[3]);
        }
        // AT fold, compile-time zero-coeff elimination (coeffs in {0,+-1}):
        // only 36/64 products nonzero across taps -> 72 adds/thread/tap.
        int i_ = tap >> 2, j_ = tap & 3;
        float c00 = AT0[i_] * AT0[j_];
        float c01 = AT0[i_] * AT1[j_];
        float c10 = AT1[i_] * AT0[j_];
        float c11 = AT1[i_] * AT1[j_];
#pragma unroll
        for (int mi = 0; mi < 2; mi++)
#pragma unroll
            for (int ni = 0; ni < 4; ni++)
#pragma unroll
                for (int q = 0; q < 4; q++) {
                    float v = mfr[mi][ni][q];
                    if (c00 != 0.f) oacc[mi][ni][q][0] += (c00 > 0.f) ? v : -v;
                    if (c01 != 0.f) oacc[mi][ni][q][1] += (c01 > 0.f) ? v : -v;
                    if (c10 != 0.f) oacc[mi][ni][q][2] += (c10 > 0.f) ? v : -v;
                    if (c11 != 0.f) oacc[mi][ni][q][3] += (c11 > 0.f) ? v : -v;
                }
    }

    // Epilogue: stage in SMEM for coalesced NCHW writes
    __syncthreads();
    float* ep = (float*)sm;               // [128 tiles][261] floats
    int g = l >> 2, tg = l & 3;
#pragma unroll
    for (int mi = 0; mi < 2; mi++)
#pragma unroll
        for (int ni = 0; ni < 4; ni++)
#pragma unroll
            for (int q = 0; q < 4; q++) {
                int tl = wm * 32 + mi * 16 + g + (q >> 1) * 8;
                int ol = wn * 32 + ni * 8 + tg * 2 + (q & 1);
#pragma unroll
                for (int e = 0; e < 4; e++)
                    ep[tl * 261 + ol * 4 + e] = oacc[mi][ni][q][e];
            }
    __syncthreads();

    float sx = *sxp;
    int tile = t >> 1;                    // 0..127
    int y    = t & 1;
    int tidg = tid0 + tile;
    int b  = tidg / TPI;
    int rr = tidg - b * TPI;
    int ti = rr / TROW, tj = rr - ti * TROW;
    size_t obase = (size_t)b * O_ * HW_ + 2 * ti * W_ + 2 * tj + y;
#pragma unroll 8
    for (int ol = 0; ol < 64; ol++) {
        int o = o0 + ol;
        float sc = sx * g_sw[o];
        float bo = bias[o];
        size_t ob = obase + (size_t)o * HW_;
        out[ob]      = ep[tile * 261 + ol * 4 + y]     * sc + bo;   // xx=0
        out[ob + W_] = ep[tile * 261 + ol * 4 + 2 + y] * sc + bo;   // xx=1
    }
}

// ---------------------------------------------------------------------------
extern "C" void kernel_launch(void* const* d_in, const int* in_sizes, int n_in,
                              void* d_out, int out_size)
{
    const float* x       = (const float*)d_in[0];   // [32,128,56,56]
    const float* weight  = (const float*)d_in[1];   // [256,128,3,3]
    const float* bias    = (const float*)d_in[2];   // [256]
    const float* scale_x = (const float*)d_in[3];   // scalar
    // d_in[4] = lut (unused; fp16 Winograd arithmetic is exact for int8 data)
    float* out = (float*)d_out;

    cudaFuncSetAttribute(wino_x_kernel,
                         cudaFuncAttributeMaxDynamicSharedMemorySize, XSMEM);
    cudaFuncSetAttribute(wino_gemm_kernel,
                         cudaFuncAttributeMaxDynamicSharedMemorySize, GSMEM);

    wino_x_kernel<<<B_ * TROW, 256, XSMEM>>>(x, scale_x);
    wino_w_kernel<<<O_, 128>>>(weight);
    wino_gemm_kernel<<<dim3(4, NT / 128), 256, GSMEM>>>(scale_x, bias, out);
}

// round 15
// speedup vs baseline: 1.0534x; 1.0534x over previous
#include <cuda_runtime.h>
#include <cuda_fp16.h>
#include <stdint.h>

#define B_   32
#define C_   128
#define H_   56
#define W_   56
#define O_   256
#define HW_  3136
#define TROW 28          // tiles per row
#define TPI  784         // tiles per image
#define NT   25088       // total 4x4 tiles (B_*TPI)

// Scratch (__device__ globals, allocation-free rule)
__device__ __align__(16) __half g_V[(size_t)16 * NT * 128];   // [tap][tile][c]  ~103MB
__device__ __align__(16) __half g_U[(size_t)16 * O_ * 128];   // [tap][o][c]     1MB
__device__ float g_sw[O_];

// ---------------------------------------------------------------------------
// PTX helpers (base ISA, valid on plain sm_103 target)
// ---------------------------------------------------------------------------
__device__ __forceinline__ void cp16(uint32_t dst, const void* src) {
    asm volatile("cp.async.cg.shared.global [%0], [%1], 16;\n"
                 :: "r"(dst), "l"(__cvta_generic_to_global(src)));
}
__device__ __forceinline__ void cp_commit() { asm volatile("cp.async.commit_group;\n" ::); }
template<int N> __device__ __forceinline__ void cp_wait() {
    asm volatile("cp.async.wait_group %0;\n" :: "n"(N));
}
__device__ __forceinline__ void ldsm4(uint32_t* r, uint32_t addr) {
    asm volatile("ldmatrix.sync.aligned.m8n8.x4.shared.b16 {%0,%1,%2,%3}, [%4];\n"
                 : "=r"(r[0]), "=r"(r[1]), "=r"(r[2]), "=r"(r[3]) : "r"(addr));
}
__device__ __forceinline__ void mma_f16(float* c, const uint32_t* a, uint32_t b0, uint32_t b1) {
    asm volatile("mma.sync.aligned.m16n8k16.row.col.f32.f16.f16.f32 "
                 "{%0,%1,%2,%3}, {%4,%5,%6,%7}, {%8,%9}, {%0,%1,%2,%3};\n"
                 : "+f"(c[0]), "+f"(c[1]), "+f"(c[2]), "+f"(c[3])
                 : "r"(a[0]), "r"(a[1]), "r"(a[2]), "r"(a[3]), "r"(b0), "r"(b1));
}

// Fast exact-nearest quantize: round true quotient x/s to nearest int.
__device__ __forceinline__ float qround(float v, float inv, float s, float hs) {
    float n = rintf(v * inv);
    float d = fmaf(-n, s, v);
    n += (d > hs) ? 1.f : 0.f;
    n -= (d < -hs) ? 1.f : 0.f;
    return fminf(fmaxf(n, -127.f), 127.f);
}

// ---------------------------------------------------------------------------
// 1) x -> quantize -> Winograd input transform -> g_V[tap][tile][c].
//    (R13 version — measured 50.8us.)
// ---------------------------------------------------------------------------
#define XSTRIDE 60       // bytes per (row,c) line
#define XSMEM (4 * 128 * XSTRIDE)   // 30720 B

__global__ __launch_bounds__(256) void wino_x_kernel(const float* __restrict__ x,
                                                     const float* __restrict__ sxp)
{
    extern __shared__ int8_t sq[];
    int t = threadIdx.x;
    int bi = blockIdx.x / TROW, ti = blockIdx.x % TROW;
    float s = *sxp;
    float inv = 1.0f / s;
    float hs = 0.5f * s;

    // Load + quantize: 4 rows (2ti-1..2ti+2) x 128 ch x 56 w -> int8 smem
#pragma unroll 4
    for (int i = 0; i < 28; i++) {
        int idx = t + 256 * i;             // 0..7167 = 4*128*14-1
        int w4 = idx % 14;
        int cr = idx / 14;
        int c = cr & 127, j = cr >> 7;
        int row = 2 * ti - 1 + j;
        float4 v = make_float4(0.f, 0.f, 0.f, 0.f);
        if (row >= 0 && row < H_)
            v = *(const float4*)(x + ((size_t)bi * C_ + c) * HW_ + row * W_ + w4 * 4);
        int q0 = (int)qround(v.x, inv, s, hs);
        int q1 = (int)qround(v.y, inv, s, hs);
        int q2 = (int)qround(v.z, inv, s, hs);
        int q3 = (int)qround(v.w, inv, s, hs);
        uint32_t pk = (uint32_t)(q0 & 0xFF) | ((uint32_t)(q1 & 0xFF) << 8)
                    | ((uint32_t)(q2 & 0xFF) << 16) | ((uint32_t)(q3 & 0xFF) << 24);
        *(uint32_t*)(sq + (j * 128 + c) * XSTRIDE + w4 * 4) = pk;
    }
    __syncthreads();

    // Transform: item = (tj, c)
#pragma unroll 2
    for (int i = 0; i < 14; i++) {
        int idx = t + 256 * i;             // 0..3583
        int c = idx & 127, tj = idx >> 7;
        float d[4][4];
#pragma unroll
        for (int r = 0; r < 4; r++)
#pragma unroll
            for (int wc = 0; wc < 4; wc++) {
                int w = 2 * tj - 1 + wc;
                d[r][wc] = (w >= 0 && w < W_)
                    ? (float)sq[(r * 128 + c) * XSTRIDE + w] : 0.f;
            }
        float e[4][4];
#pragma unroll
        for (int j = 0; j < 4; j++) {
            e[0][j] = d[0][j] - d[2][j];
            e[1][j] = d[1][j] + d[2][j];
            e[2][j] = d[2][j] - d[1][j];
            e[3][j] = d[1][j] - d[3][j];
        }
        float vv[4][4];
#pragma unroll
        for (int r = 0; r < 4; r++) {
            vv[r][0] = e[r][0] - e[r][2];
            vv[r][1] = e[r][1] + e[r][2];
            vv[r][2] = e[r][2] - e[r][1];
            vv[r][3] = e[r][1] - e[r][3];
        }
        int tid = bi * TPI + ti * TROW + tj;
#pragma unroll
        for (int r = 0; r < 4; r++)
#pragma unroll
            for (int j = 0; j < 4; j++)
                g_V[((size_t)(r * 4 + j) * NT + tid) * 128 + c] = __float2half_rn(vv[r][j]);
    }
}

// ---------------------------------------------------------------------------
// 2) weight: per-o dynamic scale = max|w|/127, quantize, Winograd filter
//    transform -> g_U[tap][o][c]  (fp16 exact: quarter-multiples, |.| <= 286)
// ---------------------------------------------------------------------------
__global__ __launch_bounds__(128) void wino_w_kernel(const float* __restrict__ w)
{
    int o = blockIdx.x, t = threadIdx.x;
    const float* wo = w + (size_t)o * 1152;

    float m = 0.f;
    for (int i = t; i < 1152; i += 128) m = fmaxf(m, fabsf(wo[i]));
#pragma unroll
    for (int off = 16; off; off >>= 1) m = fmaxf(m, __shfl_xor_sync(0xFFFFFFFFu, m, off));
    __shared__ float red[4];
    if ((t & 31) == 0) red[t >> 5] = m;
    __syncthreads();
    m = fmaxf(fmaxf(red[0], red[1]), fmaxf(red[2], red[3]));
    float scale = m / 127.0f;
    if (t == 0) g_sw[o] = scale;

    int c = t;   // 128 threads == 128 channels
    float g[3][3];
#pragma unroll
    for (int kh = 0; kh < 3; kh++)
#pragma unroll
        for (int kw = 0; kw < 3; kw++) {
            float q = rintf(wo[c * 9 + kh * 3 + kw] / scale);
            g[kh][kw] = fminf(fmaxf(q, -127.f), 127.f);
        }
    float f[4][3];
#pragma unroll
    for (int j = 0; j < 3; j++) {
        f[0][j] = g[0][j];
        f[1][j] = (g[0][j] + g[1][j] + g[2][j]) * 0.5f;
        f[2][j] = (g[0][j] - g[1][j] + g[2][j]) * 0.5f;
        f[3][j] = g[2][j];
    }
#pragma unroll
    for (int r = 0; r < 4; r++) {
        float u0 = f[r][0];
        float u1 = (f[r][0] + f[r][1] + f[r][2]) * 0.5f;
        float u2 = (f[r][0] - f[r][1] + f[r][2]) * 0.5f;
        float u3 = f[r][2];
        g_U[((size_t)(r * 4 + 0) * O_ + o) * 128 + c] = __float2half_rn(u0);
        g_U[((size_t)(r * 4 + 1) * O_ + o) * 128 + c] = __float2half_rn(u1);
        g_U[((size_t)(r * 4 + 2) * O_ + o) * 128 + c] = __float2half_rn(u2);
        g_U[((size_t)(r * 4 + 3) * O_ + o) * 128 + c] = __float2half_rn(u3);
    }
}

// ---------------------------------------------------------------------------
// 3) Winograd GEMM — R13 mainloop (3-stage ring, wait<1>, FFMA fold) with a
//    DIRECT register->gmem epilogue (no smem staging, no epilogue barriers).
// ---------------------------------------------------------------------------
#define GSTRIDE 272                       // bytes per 256B row (+16 pad)
#define GABYTES (128 * GSTRIDE)           // 34816
#define GBBYTES (64 * GSTRIDE)            // 17408
#define GSTAGE  (GABYTES + GBBYTES)       // 52224
#define GSMEM   (3 * GSTAGE)              // 156672

__global__ __launch_bounds__(256, 1)
void wino_gemm_kernel(const float* __restrict__ sxp,
                      const float* __restrict__ bias,
                      float* __restrict__ out)
{
    extern __shared__ char sm[];
    uint32_t sbase = (uint32_t)__cvta_generic_to_shared(sm);
    int t = threadIdx.x;
    int wid = t >> 5, l = t & 31;
    int wm = wid & 3, wn = wid >> 2;      // warp tile: 32 tiles x 32 o
    int o0 = blockIdx.x * 64;             // o-block fastest -> V shared in L2
    int tid0 = blockIdx.y * 128;

    float oacc[2][4][4][4];               // [mi][ni][q][e]
#pragma unroll
    for (int mi = 0; mi < 2; mi++)
#pragma unroll
        for (int ni = 0; ni < 4; ni++)
#pragma unroll
            for (int q = 0; q < 4; q++)
#pragma unroll
                for (int e = 0; e < 4; e++) oacc[mi][ni][q][e] = 0.f;

    uint32_t aOff0 = (uint32_t)((wm * 32 + (l & 15)) * GSTRIDE + (l >> 4) * 16);
    uint32_t aOff1 = aOff0 + 16u * GSTRIDE;
    uint32_t bOff0 = (uint32_t)(GABYTES + (wn * 32 + (l & 7) + (l >> 4) * 8) * GSTRIDE
                                + ((l >> 3) & 1) * 16);
    uint32_t bOff1 = bOff0 + 16u * GSTRIDE;

    auto load_stage = [&](int tap, int stg) {
        const __half* Vs = g_V + ((size_t)tap * NT + tid0) * 128;
        const __half* Us = g_U + ((size_t)tap * O_ + o0) * 128;
        uint32_t base = sbase + stg * GSTAGE;
#pragma unroll
        for (int i = 0; i < 8; i++) {
            int idx = t + 256 * i;        // A: 128 rows x 16 chunks
            int row = idx >> 4, jj = idx & 15;
            cp16(base + row * GSTRIDE + jj * 16, Vs + row * 128 + jj * 8);
        }
#pragma unroll
        for (int i = 0; i < 4; i++) {
            int idx = t + 256 * i;        // B: 64 rows x 16 chunks
            int row = idx >> 4, jj = idx & 15;
            cp16(base + GABYTES + row * GSTRIDE + jj * 16, Us + row * 128 + jj * 8);
        }
    };

    const float AT0[4] = {1.f, 1.f, 1.f, 0.f};
    const float AT1[4] = {0.f, 1.f, -1.f, -1.f};

    load_stage(0, 0); cp_commit();
    load_stage(1, 1); cp_commit();

#pragma unroll
    for (int tap = 0; tap < 16; tap++) {
        cp_wait<1>();
        __syncthreads();
        if (tap + 2 < 16) load_stage(tap + 2, (tap + 2) % 3);
        cp_commit();

        uint32_t base = sbase + (tap % 3) * GSTAGE;
        float mfr[2][4][4] = {};
#pragma unroll
        for (int ks = 0; ks < 8; ks++) {
            uint32_t a0[4], a1[4], b0[4], b1[4];
            ldsm4(a0, base + aOff0 + ks * 32);
            ldsm4(a1, base + aOff1 + ks * 32);
            ldsm4(b0, base + bOff0 + ks * 32);
            ldsm4(b1, base + bOff1 + ks * 32);
            mma_f16(mfr[0][0], a0, b0[0], b0[1]);
            mma_f16(mfr[0][1], a0, b0[2], b0[3]);
            mma_f16(mfr[0][2], a0, b1[0], b1[1]);
            mma_f16(mfr[0][3], a0, b1[2], b1[3]);
            mma_f16(mfr[1][0], a1, b0[0], b0[1]);
            mma_f16(mfr[1][1], a1, b0[2], b0[3]);
            mma_f16(mfr[1][2], a1, b1[0], b1[1]);
            mma_f16(mfr[1][3], a1, b1[2], b1[3]);
        }
        // Incremental output transform: out_xy += AT[x][i]*AT[y][j] * Mhat_ij
        int i_ = tap >> 2, j_ = tap & 3;
        float c00 = AT0[i_] * AT0[j_];
        float c01 = AT0[i_] * AT1[j_];
        float c10 = AT1[i_] * AT0[j_];
        float c11 = AT1[i_] * AT1[j_];
#pragma unroll
        for (int mi = 0; mi < 2; mi++)
#pragma unroll
            for (int ni = 0; ni < 4; ni++)
#pragma unroll
                for (int q = 0; q < 4; q++) {
                    float v = mfr[mi][ni][q];
                    oacc[mi][ni][q][0] += c00 * v;
                    oacc[mi][ni][q][1] += c01 * v;
                    oacc[mi][ni][q][2] += c10 * v;
                    oacc[mi][ni][q][3] += c11 * v;
                }
    }

    // Direct epilogue: register fragments -> gmem. Per (mi,qh): one tile row;
    // per (ni,ql): one o. y-pair (e, e+1) contiguous -> float2 stores; warp's
    // 8 g-lanes cover 16 consecutive floats -> full 32B sectors.
    float sx = *sxp;
    int g = l >> 2, tg = l & 3;
#pragma unroll
    for (int mi = 0; mi < 2; mi++) {
#pragma unroll
        for (int qh = 0; qh < 2; qh++) {
            int tile = tid0 + wm * 32 + mi * 16 + qh * 8 + g;
            int b  = tile / TPI;
            int rr = tile - b * TPI;
            int ti = rr / TROW, tj = rr - ti * TROW;
            size_t pbase = (size_t)b * O_ * HW_ + (size_t)(2 * ti) * W_ + 2 * tj;
#pragma unroll
            for (int ni = 0; ni < 4; ni++) {
#pragma unroll
                for (int ql = 0; ql < 2; ql++) {
                    int o = o0 + wn * 32 + ni * 8 + tg * 2 + ql;
                    float sc = sx * g_sw[o];
                    float bo = bias[o];
                    int q = qh * 2 + ql;
                    size_t ob = pbase + (size_t)o * HW_;
#pragma unroll
                    for (int xx = 0; xx < 2; xx++) {
                        float2 vv;
                        vv.x = oacc[mi][ni][q][xx * 2 + 0] * sc + bo;
                        vv.y = oacc[mi][ni][q][xx * 2 + 1] * sc + bo;
                        *(float2*)(out + ob + (size_t)xx * W_) = vv;
                    }
                }
            }
        }
    }
}

// ---------------------------------------------------------------------------
extern "C" void kernel_launch(void* const* d_in, const int* in_sizes, int n_in,
                              void* d_out, int out_size)
{
    const float* x       = (const float*)d_in[0];   // [32,128,56,56]
    const float* weight  = (const float*)d_in[1];   // [256,128,3,3]
    const float* bias    = (const float*)d_in[2];   // [256]
    const float* scale_x = (const float*)d_in[3];   // scalar
    // d_in[4] = lut (unused; fp16 Winograd arithmetic is exact for int8 data)
    float* out = (float*)d_out;

    cudaFuncSetAttribute(wino_x_kernel,
                         cudaFuncAttributeMaxDynamicSharedMemorySize, XSMEM);
    cudaFuncSetAttribute(wino_gemm_kernel,
                         cudaFuncAttributeMaxDynamicSharedMemorySize, GSMEM);

    wino_x_kernel<<<B_ * TROW, 256, XSMEM>>>(x, scale_x);
    wino_w_kernel<<<O_, 128>>>(weight);
    wino_gemm_kernel<<<dim3(4, NT / 128), 256, GSMEM>>>(scale_x, bias, out);
}

// round 16
// speedup vs baseline: 1.1068x; 1.0507x over previous
#include <cuda_runtime.h>
#include <cuda_fp16.h>
#include <stdint.h>

#define B_   32
#define C_   128
#define H_   56
#define W_   56
#define O_   256
#define HW_  3136
#define TROW 28          // tiles per row
#define TPI  784         // tiles per image
#define NT   25088       // total 4x4 tiles (B_*TPI)

// Scratch (__device__ globals, allocation-free rule)
__device__ __align__(16) __half g_V[(size_t)16 * NT * 128];   // [tap][tile][c]  ~103MB
__device__ __align__(16) __half g_U[(size_t)16 * O_ * 128];   // [tap][o][c]     1MB
__device__ float g_sw[O_];

// ---------------------------------------------------------------------------
// PTX helpers (base ISA, valid on plain sm_103 target)
// ---------------------------------------------------------------------------
__device__ __forceinline__ void cp16(uint32_t dst, const void* src) {
    asm volatile("cp.async.cg.shared.global [%0], [%1], 16;\n"
                 :: "r"(dst), "l"(__cvta_generic_to_global(src)));
}
__device__ __forceinline__ void cp_commit() { asm volatile("cp.async.commit_group;\n" ::); }
template<int N> __device__ __forceinline__ void cp_wait() {
    asm volatile("cp.async.wait_group %0;\n" :: "n"(N));
}
__device__ __forceinline__ void ldsm4(uint32_t* r, uint32_t addr) {
    asm volatile("ldmatrix.sync.aligned.m8n8.x4.shared.b16 {%0,%1,%2,%3}, [%4];\n"
                 : "=r"(r[0]), "=r"(r[1]), "=r"(r[2]), "=r"(r[3]) : "r"(addr));
}
__device__ __forceinline__ void mma_f16(float* c, const uint32_t* a, uint32_t b0, uint32_t b1) {
    asm volatile("mma.sync.aligned.m16n8k16.row.col.f32.f16.f16.f32 "
                 "{%0,%1,%2,%3}, {%4,%5,%6,%7}, {%8,%9}, {%0,%1,%2,%3};\n"
                 : "+f"(c[0]), "+f"(c[1]), "+f"(c[2]), "+f"(c[3])
                 : "r"(a[0]), "r"(a[1]), "r"(a[2]), "r"(a[3]), "r"(b0), "r"(b1));
}
// prmt: pack two sign-extended bytes (a.b0, b.b0) into one s16x2
__device__ __forceinline__ uint32_t prmt_pair(uint32_t a, uint32_t b) {
    uint32_t d;
    asm("prmt.b32 %0, %1, %2, 0xC480;" : "=r"(d) : "r"(a), "r"(b));
    return d;
}

// Fast exact-nearest quantize: round true quotient x/s to nearest int.
__device__ __forceinline__ float qround(float v, float inv, float s, float hs) {
    float n = rintf(v * inv);
    float d = fmaf(-n, s, v);
    n += (d > hs) ? 1.f : 0.f;
    n -= (d < -hs) ? 1.f : 0.f;
    return fminf(fmaxf(n, -127.f), 127.f);
}

// ---------------------------------------------------------------------------
// 1) x -> quantize -> Winograd input transform -> g_V[tap][tile][c].
//    Load/quantize phase: R13-proven (float4 loads, STS.32 packed).
//    Transform: channel-pair vectorized, exact s16x2 math + fp16 bias trick.
// ---------------------------------------------------------------------------
#define XSTRIDE 60       // bytes per (row,c) line
#define XSMEM (4 * 128 * XSTRIDE)   // 30720 B

__global__ __launch_bounds__(256) void wino_x_kernel(const float* __restrict__ x,
                                                     const float* __restrict__ sxp)
{
    extern __shared__ int8_t sq[];
    int t = threadIdx.x;
    int bi = blockIdx.x / TROW, ti = blockIdx.x % TROW;
    float s = *sxp;
    float inv = 1.0f / s;
    float hs = 0.5f * s;

    // Load + quantize: 4 rows (2ti-1..2ti+2) x 128 ch x 56 w -> int8 smem
#pragma unroll 4
    for (int i = 0; i < 28; i++) {
        int idx = t + 256 * i;             // 0..7167 = 4*128*14-1
        int w4 = idx % 14;
        int cr = idx / 14;
        int c = cr & 127, j = cr >> 7;
        int row = 2 * ti - 1 + j;
        float4 v = make_float4(0.f, 0.f, 0.f, 0.f);
        if (row >= 0 && row < H_)
            v = *(const float4*)(x + ((size_t)bi * C_ + c) * HW_ + row * W_ + w4 * 4);
        int q0 = (int)qround(v.x, inv, s, hs);
        int q1 = (int)qround(v.y, inv, s, hs);
        int q2 = (int)qround(v.z, inv, s, hs);
        int q3 = (int)qround(v.w, inv, s, hs);
        uint32_t pk = (uint32_t)(q0 & 0xFF) | ((uint32_t)(q1 & 0xFF) << 8)
                    | ((uint32_t)(q2 & 0xFF) << 16) | ((uint32_t)(q3 & 0xFF) << 24);
        *(uint32_t*)(sq + (j * 128 + c) * XSTRIDE + w4 * 4) = pk;
    }
    __syncthreads();

    // Transform: item = (tj, channel-pair c2); 1792 items, 7 per thread.
    const __half2 h1536 = __half2half2(__ushort_as_half(0x6600));
    const uint8_t* squ = (const uint8_t*)sq;
#pragma unroll
    for (int i = 0; i < 7; i++) {
        int idx = t + 256 * i;             // 0..1791
        int c2 = idx & 63, tj = idx >> 6;
        int c = 2 * c2;
        const uint8_t* p0 = squ + c * XSTRIDE;          // channel c
        const uint8_t* p1 = squ + (c + 1) * XSTRIDE;    // channel c+1

        // d[r][wc] = s16x2(chan c, chan c+1)
        uint32_t d[4][4];
#pragma unroll
        for (int r = 0; r < 4; r++)
#pragma unroll
            for (int wc = 0; wc < 4; wc++) {
                int w = 2 * tj - 1 + wc;
                uint32_t dd = 0u;
                if (w >= 0 && w < W_) {
                    uint32_t b0 = p0[r * (128 * XSTRIDE) + w];
                    uint32_t b1 = p1[r * (128 * XSTRIDE) + w];
                    dd = prmt_pair(b0, b1);
                }
                d[r][wc] = dd;
            }
        // Row stage (exact s16x2): e[r'][wc]
        uint32_t e0[4], e1[4], e2[4], e3[4];
#pragma unroll
        for (int wc = 0; wc < 4; wc++) {
            e0[wc] = __vsub2(d[0][wc], d[2][wc]);
            e1[wc] = __vadd2(d[1][wc], d[2][wc]);
            e2[wc] = __vsub2(d[2][wc], d[1][wc]);
            e3[wc] = __vsub2(d[1][wc], d[3][wc]);
        }
        int tid = bi * TPI + ti * TROW + tj;
        __half* vb = g_V + (size_t)tid * 128 + c;
        // Col stage + fp16 bias-trick convert + STG.32 per tap
#pragma unroll
        for (int r = 0; r < 4; r++) {
            const uint32_t* er = (r == 0) ? e0 : (r == 1) ? e1 : (r == 2) ? e2 : e3;
            uint32_t vv[4];
            vv[0] = __vsub2(er[0], er[2]);
            vv[1] = __vadd2(er[1], er[2]);
            vv[2] = __vsub2(er[2], er[1]);
            vv[3] = __vsub2(er[1], er[3]);
#pragma unroll
            for (int j = 0; j < 4; j++) {
                uint32_t bl = __vadd2(vv[j], 0x66006600u);
                __half2 res = __hsub2(*(__half2*)&bl, h1536);
                *(uint32_t*)(vb + (size_t)(r * 4 + j) * NT * 128) = *(uint32_t*)&res;
            }
        }
    }
}

// ---------------------------------------------------------------------------
// 2) weight: per-o dynamic scale = max|w|/127, quantize, Winograd filter
//    transform -> g_U[tap][o][c]  (fp16 exact: quarter-multiples, |.| <= 286)
// ---------------------------------------------------------------------------
__global__ __launch_bounds__(128) void wino_w_kernel(const float* __restrict__ w)
{
    int o = blockIdx.x, t = threadIdx.x;
    const float* wo = w + (size_t)o * 1152;

    float m = 0.f;
    for (int i = t; i < 1152; i += 128) m = fmaxf(m, fabsf(wo[i]));
#pragma unroll
    for (int off = 16; off; off >>= 1) m = fmaxf(m, __shfl_xor_sync(0xFFFFFFFFu, m, off));
    __shared__ float red[4];
    if ((t & 31) == 0) red[t >> 5] = m;
    __syncthreads();
    m = fmaxf(fmaxf(red[0], red[1]), fmaxf(red[2], red[3]));
    float scale = m / 127.0f;
    if (t == 0) g_sw[o] = scale;

    int c = t;   // 128 threads == 128 channels
    float g[3][3];
#pragma unroll
    for (int kh = 0; kh < 3; kh++)
#pragma unroll
        for (int kw = 0; kw < 3; kw++) {
            float q = rintf(wo[c * 9 + kh * 3 + kw] / scale);
            g[kh][kw] = fminf(fmaxf(q, -127.f), 127.f);
        }
    float f[4][3];
#pragma unroll
    for (int j = 0; j < 3; j++) {
        f[0][j] = g[0][j];
        f[1][j] = (g[0][j] + g[1][j] + g[2][j]) * 0.5f;
        f[2][j] = (g[0][j] - g[1][j] + g[2][j]) * 0.5f;
        f[3][j] = g[2][j];
    }
#pragma unroll
    for (int r = 0; r < 4; r++) {
        float u0 = f[r][0];
        float u1 = (f[r][0] + f[r][1] + f[r][2]) * 0.5f;
        float u2 = (f[r][0] - f[r][1] + f[r][2]) * 0.5f;
        float u3 = f[r][2];
        g_U[((size_t)(r * 4 + 0) * O_ + o) * 128 + c] = __float2half_rn(u0);
        g_U[((size_t)(r * 4 + 1) * O_ + o) * 128 + c] = __float2half_rn(u1);
        g_U[((size_t)(r * 4 + 2) * O_ + o) * 128 + c] = __float2half_rn(u2);
        g_U[((size_t)(r * 4 + 3) * O_ + o) * 128 + c] = __float2half_rn(u3);
    }
}

// ---------------------------------------------------------------------------
// 3) Winograd GEMM — R15 verbatim (3-stage ring, wait<1>, FFMA fold,
//    direct register->gmem epilogue). Measured ~144us.
// ---------------------------------------------------------------------------
#define GSTRIDE 272                       // bytes per 256B row (+16 pad)
#define GABYTES (128 * GSTRIDE)           // 34816
#define GBBYTES (64 * GSTRIDE)            // 17408
#define GSTAGE  (GABYTES + GBBYTES)       // 52224
#define GSMEM   (3 * GSTAGE)              // 156672

__global__ __launch_bounds__(256, 1)
void wino_gemm_kernel(const float* __restrict__ sxp,
                      const float* __restrict__ bias,
                      float* __restrict__ out)
{
    extern __shared__ char sm[];
    uint32_t sbase = (uint32_t)__cvta_generic_to_shared(sm);
    int t = threadIdx.x;
    int wid = t >> 5, l = t & 31;
    int wm = wid & 3, wn = wid >> 2;      // warp tile: 32 tiles x 32 o
    int o0 = blockIdx.x * 64;             // o-block fastest -> V shared in L2
    int tid0 = blockIdx.y * 128;

    float oacc[2][4][4][4];               // [mi][ni][q][e]
#pragma unroll
    for (int mi = 0; mi < 2; mi++)
#pragma unroll
        for (int ni = 0; ni < 4; ni++)
#pragma unroll
            for (int q = 0; q < 4; q++)
#pragma unroll
                for (int e = 0; e < 4; e++) oacc[mi][ni][q][e] = 0.f;

    uint32_t aOff0 = (uint32_t)((wm * 32 + (l & 15)) * GSTRIDE + (l >> 4) * 16);
    uint32_t aOff1 = aOff0 + 16u * GSTRIDE;
    uint32_t bOff0 = (uint32_t)(GABYTES + (wn * 32 + (l & 7) + (l >> 4) * 8) * GSTRIDE
                                + ((l >> 3) & 1) * 16);
    uint32_t bOff1 = bOff0 + 16u * GSTRIDE;

    auto load_stage = [&](int tap, int stg) {
        const __half* Vs = g_V + ((size_t)tap * NT + tid0) * 128;
        const __half* Us = g_U + ((size_t)tap * O_ + o0) * 128;
        uint32_t base = sbase + stg * GSTAGE;
#pragma unroll
        for (int i = 0; i < 8; i++) {
            int idx = t + 256 * i;        // A: 128 rows x 16 chunks
            int row = idx >> 4, jj = idx & 15;
            cp16(base + row * GSTRIDE + jj * 16, Vs + row * 128 + jj * 8);
        }
#pragma unroll
        for (int i = 0; i < 4; i++) {
            int idx = t + 256 * i;        // B: 64 rows x 16 chunks
            int row = idx >> 4, jj = idx & 15;
            cp16(base + GABYTES + row * GSTRIDE + jj * 16, Us + row * 128 + jj * 8);
        }
    };

    const float AT0[4] = {1.f, 1.f, 1.f, 0.f};
    const float AT1[4] = {0.f, 1.f, -1.f, -1.f};

    load_stage(0, 0); cp_commit();
    load_stage(1, 1); cp_commit();

#pragma unroll
    for (int tap = 0; tap < 16; tap++) {
        cp_wait<1>();
        __syncthreads();
        if (tap + 2 < 16) load_stage(tap + 2, (tap + 2) % 3);
        cp_commit();

        uint32_t base = sbase + (tap % 3) * GSTAGE;
        float mfr[2][4][4] = {};
#pragma unroll
        for (int ks = 0; ks < 8; ks++) {
            uint32_t a0[4], a1[4], b0[4], b1[4];
            ldsm4(a0, base + aOff0 + ks * 32);
            ldsm4(a1, base + aOff1 + ks * 32);
            ldsm4(b0, base + bOff0 + ks * 32);
            ldsm4(b1, base + bOff1 + ks * 32);
            mma_f16(mfr[0][0], a0, b0[0], b0[1]);
            mma_f16(mfr[0][1], a0, b0[2], b0[3]);
            mma_f16(mfr[0][2], a0, b1[0], b1[1]);
            mma_f16(mfr[0][3], a0, b1[2], b1[3]);
            mma_f16(mfr[1][0], a1, b0[0], b0[1]);
            mma_f16(mfr[1][1], a1, b0[2], b0[3]);
            mma_f16(mfr[1][2], a1, b1[0], b1[1]);
            mma_f16(mfr[1][3], a1, b1[2], b1[3]);
        }
        // Incremental output transform: out_xy += AT[x][i]*AT[y][j] * Mhat_ij
        int i_ = tap >> 2, j_ = tap & 3;
        float c00 = AT0[i_] * AT0[j_];
        float c01 = AT0[i_] * AT1[j_];
        float c10 = AT1[i_] * AT0[j_];
        float c11 = AT1[i_] * AT1[j_];
#pragma unroll
        for (int mi = 0; mi < 2; mi++)
#pragma unroll
            for (int ni = 0; ni < 4; ni++)
#pragma unroll
                for (int q = 0; q < 4; q++) {
                    float v = mfr[mi][ni][q];
                    oacc[mi][ni][q][0] += c00 * v;
                    oacc[mi][ni][q][1] += c01 * v;
                    oacc[mi][ni][q][2] += c10 * v;
                    oacc[mi][ni][q][3] += c11 * v;
                }
    }

    // Direct epilogue: register fragments -> gmem (sector-aligned float2s).
    float sx = *sxp;
    int g = l >> 2, tg = l & 3;
#pragma unroll
    for (int mi = 0; mi < 2; mi++) {
#pragma unroll
        for (int qh = 0; qh < 2; qh++) {
            int tile = tid0 + wm * 32 + mi * 16 + qh * 8 + g;
            int b  = tile / TPI;
            int rr = tile - b * TPI;
            int ti = rr / TROW, tj = rr - ti * TROW;
            size_t pbase = (size_t)b * O_ * HW_ + (size_t)(2 * ti) * W_ + 2 * tj;
#pragma unroll
            for (int ni = 0; ni < 4; ni++) {
#pragma unroll
                for (int ql = 0; ql < 2; ql++) {
                    int o = o0 + wn * 32 + ni * 8 + tg * 2 + ql;
                    float sc = sx * g_sw[o];
                    float bo = bias[o];
                    int q = qh * 2 + ql;
                    size_t ob = pbase + (size_t)o * HW_;
#pragma unroll
                    for (int xx = 0; xx < 2; xx++) {
                        float2 vv;
                        vv.x = oacc[mi][ni][q][xx * 2 + 0] * sc + bo;
                        vv.y = oacc[mi][ni][q][xx * 2 + 1] * sc + bo;
                        *(float2*)(out + ob + (size_t)xx * W_) = vv;
                    }
                }
            }
        }
    }
}

// ---------------------------------------------------------------------------
extern "C" void kernel_launch(void* const* d_in, const int* in_sizes, int n_in,
                              void* d_out, int out_size)
{
    const float* x       = (const float*)d_in[0];   // [32,128,56,56]
    const float* weight  = (const float*)d_in[1];   // [256,128,3,3]
    const float* bias    = (const float*)d_in[2];   // [256]
    const float* scale_x = (const float*)d_in[3];   // scalar
    // d_in[4] = lut (unused; fp16 Winograd arithmetic is exact for int8 data)
    float* out = (float*)d_out;

    cudaFuncSetAttribute(wino_x_kernel,
                         cudaFuncAttributeMaxDynamicSharedMemorySize, XSMEM);
    cudaFuncSetAttribute(wino_gemm_kernel,
                         cudaFuncAttributeMaxDynamicSharedMemorySize, GSMEM);

    wino_x_kernel<<<B_ * TROW, 256, XSMEM>>>(x, scale_x);
    wino_w_kernel<<<O_, 128>>>(weight);
    wino_gemm_kernel<<<dim3(4, NT / 128), 256, GSMEM>>>(scale_x, bias, out);
}